// round 9
// baseline (speedup 1.0000x reference)
#include <cuda_runtime.h>
#include <cstdint>

// PackedViterbi (logsumexp semiring) forward — two-phase warp groups.
// theta: [T=256, B=32, S=128, S=128] fp32.  out: [B=32] fp32.
//
// 32 clusters x 4 CTAs (one per batch), 256 threads per CTA.
// Group A (warps 0-3) executes even timesteps, group B (warps 4-7) odd ones.
// Per step: poll own tagged exp-domain DSMEM slot, named barrier (128),
// conflict-free packet dot (4 lanes/row x 32 j), 2 shfls, renorm, 4-way
// parallel fan-out send. The exp2(theta) transform for t+2 runs AFTER the
// send — overlapped with the other group's chain and the packet transit.
// No MUFU op on the serial chain. Padded (132-float) ring rows.

#define NT    256
#define NB    32
#define NS    128
#define SUBS  4
#define NTHR  256
#define ROWF  132                       // padded floats per ring row
#define SLOT_BYTES (32 * ROWF * 4)      // 16896
#define NSLOT 3                         // ring slots per group
#define LOG2E 1.4426950408889634f
#define FULLM 0xffffffffu

static __device__ __forceinline__ float ex2f_(float x) {
    float y; asm("ex2.approx.ftz.f32 %0, %1;" : "=f"(y) : "f"(x)); return y;
}
static __device__ __forceinline__ float lg2f_(float x) {
    float y; asm("lg2.approx.ftz.f32 %0, %1;" : "=f"(y) : "f"(x)); return y;
}
static __device__ __forceinline__ void cp16(unsigned d, const void* s) {
    asm volatile("cp.async.cg.shared.global [%0], [%1], 16;" :: "r"(d), "l"(s));
}
static __device__ __forceinline__ void st_dsmem64(unsigned daddr, unsigned long long v) {
    asm volatile("st.relaxed.cluster.shared::cluster.b64 [%0], %1;"
                 :: "r"(daddr), "l"(v) : "memory");
}
static __device__ __forceinline__ void bar_s(int id) {
    asm volatile("bar.sync %0, 128;" :: "r"(id) : "memory");
}

extern "C" __global__ void __launch_bounds__(NTHR, 1) __cluster_dims__(SUBS, 1, 1)
viterbi_fwd(const float* __restrict__ theta, float* __restrict__ out)
{
    extern __shared__ float ring[];                          // 2*NSLOT*SLOT_BYTES
    __shared__ __align__(16) unsigned long long sV[2][NS];   // tagged exp-domain V
    __shared__ int s_offB;

    const int tid  = threadIdx.x;
    const int lane = tid & 31;
    const int warp = tid >> 5;
    const int g    = warp >> 2;        // 0 = group A (even t), 1 = group B (odd t)
    const int gw   = warp & 3;         // warp within group
    const int gtid = tid & 127;
    const int q    = lane & 3;         // 4 lanes per row; also target rank
    const int rp   = lane >> 2;        // row within warp, 0..7
    const int rowL = gw * 8 + rp;      // local row 0..31
    const int bid  = blockIdx.x;
    const int bb   = bid >> 2;         // batch
    const int sub  = bid & 3;          // cluster rank
    const int irow = sub * 32 + rowL;  // global state index i

    unsigned rbase = (unsigned)__cvta_generic_to_shared(ring)
                   + (unsigned)(g * NSLOT * SLOT_BYTES);
    unsigned vbase = (unsigned)__cvta_generic_to_shared(&sV[0][0]);

    ((unsigned long long*)sV)[tid] = 0ull;   // zero all 256 tag slots
    __syncthreads();
    asm volatile("barrier.cluster.arrive.aligned;" ::: "memory");
    asm volatile("barrier.cluster.wait.aligned;"   ::: "memory");

    unsigned rV[SUBS];
#pragma unroll
    for (int r = 0; r < SUBS; ++r)
        asm("mapa.shared::cluster.u32 %0, %1, %2;" : "=r"(rV[r]) : "r"(vbase), "r"(r));

    const size_t tstride = (size_t)NB * NS * NS;
    const float* myrow = theta + ((size_t)bb * NS + (size_t)(sub * 32 + rowL)) * NS;
    // per-lane copy/transform geometry
    const unsigned dst_row = (unsigned)(rowL * (ROWF * 4)) + (unsigned)(q * 128);

    // copy stage s: warp covers its 8 rows; lane copies 8 chunks of 16B
    auto copyStage = [&](int s) {
        unsigned dst = rbase + (unsigned)(((s >> 1) % NSLOT) * SLOT_BYTES) + dst_row;
        const char* src = (const char*)(myrow + (size_t)s * tstride) + q * 128;
#pragma unroll
        for (int m = 0; m < 8; ++m)
            cp16(dst + m * 16, src + m * 16);
        asm volatile("cp.async.commit_group;");
    };

    float E[32];
    // transform stage s -> E (j = 16k + 4q + 0..3)
    auto transformStage = [&](int s) {
        const float4* tp = (const float4*)
            (ring + (size_t)(g * NSLOT + (s >> 1) % NSLOT) * (SLOT_BYTES / 4)
                  + (size_t)rowL * ROWF) + q;
#pragma unroll
        for (int k = 0; k < 8; ++k) {
            float4 a = tp[4 * k];
            E[4 * k + 0] = ex2f_(a.x * LOG2E);
            E[4 * k + 1] = ex2f_(a.y * LOG2E);
            E[4 * k + 2] = ex2f_(a.z * LOG2E);
            E[4 * k + 3] = ex2f_(a.w * LOG2E);
        }
    };

    // ---- prologue: prefetch stages g, g+2, g+4; transform stage g ----
    copyStage(g);
    copyStage(g + 2);
    copyStage(g + 4);
    asm volatile("cp.async.wait_group 2;");
    transformStage(g);

    int off = 0;

    for (int t = g; t < NT; t += 2) {
        // 1. poll own slot (one volatile LDS.64), then group barrier
        if (t > 0) {
            unsigned a = vbase + (unsigned)((g * NS + gtid) * 8);
            unsigned vv, tg;
            do {
                asm volatile("ld.volatile.shared.v2.u32 {%0,%1}, [%2];"
                             : "=r"(vv), "=r"(tg) : "r"(a));
            } while (tg != (unsigned)t);
        }
        bar_s(1 + g);

        // 2. dot over 32 j's (packets tag-guaranteed after barrier)
        float c;
        int roff = 0;
        if (t == 0) {
            float a0 = 0.f, a1 = 0.f, a2 = 0.f, a3 = 0.f;
#pragma unroll
            for (int k = 0; k < 8; ++k) {
                a0 += E[4 * k];     a1 += E[4 * k + 1];
                a2 += E[4 * k + 2]; a3 += E[4 * k + 3];
            }
            c = (a0 + a1) + (a2 + a3);
        } else {
            const uint4* P = (const uint4*)&sV[g][0];
            roff = (int)(((unsigned)sV[g][0] >> 23) & 0xFF) - 127;
            float a0 = 0.f, a1 = 0.f, a2 = 0.f, a3 = 0.f;
#pragma unroll
            for (int k = 0; k < 8; ++k) {
                uint4 u0 = P[8 * k + 2 * q];
                uint4 u1 = P[8 * k + 2 * q + 1];
                a0 = fmaf(E[4 * k + 0], __uint_as_float(u0.x), a0);
                a1 = fmaf(E[4 * k + 1], __uint_as_float(u0.z), a1);
                a2 = fmaf(E[4 * k + 2], __uint_as_float(u1.x), a2);
                a3 = fmaf(E[4 * k + 3], __uint_as_float(u1.z), a3);
            }
            c = (a0 + a1) + (a2 + a3);
        }

        // 3. 4-lane reduce, renorm, parallel fan-out (lane q -> rank q)
        c += __shfl_xor_sync(FULLM, c, 1);
        c += __shfl_xor_sync(FULLM, c, 2);
        if (t > 0) {
            off += roff;
            c *= __uint_as_float((unsigned)(127 - roff) << 23);   // * 2^-roff
        }
        {
            unsigned long long pkt = ((unsigned long long)(unsigned)(t + 1) << 32)
                                   | (unsigned long long)__float_as_uint(c);
            unsigned voff = (unsigned)(((g ^ 1) * NS + irow) * 8);
            st_dsmem64(rV[q] + voff, pkt);
        }

        // 4. shadow work: transform stage t+2, prefetch stage t+6
        if (t + 2 < NT) {
            asm volatile("cp.async.wait_group 1;");
            transformStage(t + 2);
            if (t + 6 < NT) copyStage(t + 6);
            else            asm volatile("cp.async.commit_group;");  // keep count
        }
    }

    // ---- epilogue ----
    if (g == 1) {
        if (gtid == 0) s_offB = off;
    } else {
        // drain tag NT on buffer 0 (every rank, every A thread: own slot)
        unsigned a = vbase + (unsigned)(gtid * 8);
        unsigned vv, tg;
        do {
            asm volatile("ld.volatile.shared.v2.u32 {%0,%1}, [%2];"
                         : "=r"(vv), "=r"(tg) : "r"(a));
        } while (tg != (unsigned)NT);
    }
    __syncthreads();

    if (g == 0 && warp == 0 && sub == 0) {
        float x0 = __uint_as_float((unsigned)sV[0][lane]);
        float x1 = __uint_as_float((unsigned)sV[0][lane + 32]);
        float x2 = __uint_as_float((unsigned)sV[0][lane + 64]);
        float x3 = __uint_as_float((unsigned)sV[0][lane + 96]);
        float s = (x0 + x1) + (x2 + x3);
#pragma unroll
        for (int o = 16; o; o >>= 1) s += __shfl_xor_sync(FULLM, s, o);
        if (lane == 0)
            out[bb] = 0.6931471805599453f * ((float)(off + s_offB) + lg2f_(s));
    }
    asm volatile("barrier.cluster.arrive.aligned;" ::: "memory");
    asm volatile("barrier.cluster.wait.aligned;"   ::: "memory");
}

extern "C" void kernel_launch(void* const* d_in, const int* in_sizes, int n_in,
                              void* d_out, int out_size)
{
    (void)in_sizes; (void)n_in; (void)out_size;
    const float* theta = (const float*)d_in[0];
    float* out = (float*)d_out;

    cudaFuncSetAttribute(viterbi_fwd,
                         cudaFuncAttributeMaxDynamicSharedMemorySize,
                         2 * NSLOT * SLOT_BYTES);
    viterbi_fwd<<<NB * SUBS, NTHR, 2 * NSLOT * SLOT_BYTES>>>(theta, out);
}

// round 10
// speedup vs baseline: 1.7217x; 1.7217x over previous
#include <cuda_runtime.h>
#include <cstdint>

// PackedViterbi (logsumexp semiring) forward.
// theta: [T=256, B=32, S=128, S=128] fp32.  out: [B=32] fp32.
//
// R4 structure (32 clusters x 4 CTAs, 256 thr, tagged DSMEM relay, one poll
// per thread + one __syncthreads per step) with ONE structural change:
// the exp2(theta) transform for stage t+1 runs AFTER the send of V_{t+1},
// so the 256-cyc/SMSP MUFU burst overlaps the DSMEM transit instead of
// serializing before the poll.

#define NT   256
#define NB   32
#define NS   128
#define SUBS 4
#define RPC  32
#define NTHR 256
#define TILE_BYTES (RPC * NS * 4)    // 16384
#define PIPE 6
#define DIST 4
#define LOG2E 1.4426950408889634f
#define FULLM 0xffffffffu

static __device__ __forceinline__ float ex2f_(float x) {
    float y; asm("ex2.approx.ftz.f32 %0, %1;" : "=f"(y) : "f"(x)); return y;
}
static __device__ __forceinline__ float lg2f_(float x) {
    float y; asm("lg2.approx.ftz.f32 %0, %1;" : "=f"(y) : "f"(x)); return y;
}
static __device__ __forceinline__ void cp16(unsigned d, const void* s) {
    asm volatile("cp.async.cg.shared.global [%0], [%1], 16;" :: "r"(d), "l"(s));
}
static __device__ __forceinline__ void st_dsmem64(unsigned daddr, unsigned long long v) {
    asm volatile("st.relaxed.cluster.shared::cluster.b64 [%0], %1;"
                 :: "r"(daddr), "l"(v) : "memory");
}
static __device__ __forceinline__ unsigned long long ld_vol64(unsigned addr) {
    unsigned long long v;
    asm volatile("ld.volatile.shared.b64 %0, [%1];" : "=l"(v) : "r"(addr));
    return v;
}

extern "C" __global__ void __launch_bounds__(NTHR, 1) __cluster_dims__(SUBS, 1, 1)
viterbi_fwd(const float* __restrict__ theta, float* __restrict__ out)
{
    extern __shared__ float4 ring[];                         // PIPE * 1024 float4
    __shared__ __align__(16) unsigned long long sV[2][NS];   // tagged V' packets
    __shared__ float sEV[2][NS];                             // exp2(V') tables

    const int tid  = threadIdx.x;
    const int lane = tid & 31;
    const int warp = tid >> 5;
    const int sl   = lane & 7;          // 8 lanes per row
    const int rg   = lane >> 3;
    const int rowL = (warp << 2) + rg;  // local row 0..31
    const int bid  = blockIdx.x;
    const int bb   = bid >> 2;          // batch
    const int sub  = bid & 3;           // cluster rank
    const int irow = sub * RPC + rowL;  // global state index i

    unsigned rbase = (unsigned)__cvta_generic_to_shared(ring);
    unsigned vbase = (unsigned)__cvta_generic_to_shared(&sV[0][0]);

    // zero tags before any peer can write
    ((unsigned long long*)sV)[tid] = 0ull;
    __syncthreads();
    asm volatile("barrier.cluster.arrive.aligned;" ::: "memory");
    asm volatile("barrier.cluster.wait.aligned;"   ::: "memory");

    unsigned rV[SUBS];
#pragma unroll
    for (int r = 0; r < SUBS; ++r)
        asm("mapa.shared::cluster.u32 %0, %1, %2;" : "=r"(rV[r]) : "r"(vbase), "r"(r));

    const size_t tstride = (size_t)NB * NS * NS;
    const float* base = theta + ((size_t)bb * NS + (size_t)sub * RPC) * NS;

    // ---- prologue: prefetch stages 0..DIST-1 ----
#pragma unroll
    for (int s = 0; s < DIST; ++s) {
        const char* src = (const char*)(base + (size_t)s * tstride);
        unsigned dst = rbase + s * TILE_BYTES;
#pragma unroll
        for (int k2 = 0; k2 < 4; ++k2) {
            int o = (tid + k2 * NTHR) << 4;
            cp16(dst + o, src + o);
        }
        asm volatile("cp.async.commit_group;");
    }

    float Ea[16], Eb[16];
    float off = 0.f;

    // stage 0 -> Ea
    asm volatile("cp.async.wait_group 3;");
    __syncthreads();          // all warps' stage-0 copies visible
    {
        const float4* tp = ring + rowL * (NS / 4) + sl;
        float4 a0 = tp[0], a1 = tp[8], a2 = tp[16], a3 = tp[24];
        Ea[0]  = ex2f_(a0.x * LOG2E); Ea[1]  = ex2f_(a0.y * LOG2E);
        Ea[2]  = ex2f_(a0.z * LOG2E); Ea[3]  = ex2f_(a0.w * LOG2E);
        Ea[4]  = ex2f_(a1.x * LOG2E); Ea[5]  = ex2f_(a1.y * LOG2E);
        Ea[6]  = ex2f_(a1.z * LOG2E); Ea[7]  = ex2f_(a1.w * LOG2E);
        Ea[8]  = ex2f_(a2.x * LOG2E); Ea[9]  = ex2f_(a2.y * LOG2E);
        Ea[10] = ex2f_(a2.z * LOG2E); Ea[11] = ex2f_(a2.w * LOG2E);
        Ea[12] = ex2f_(a3.x * LOG2E); Ea[13] = ex2f_(a3.y * LOG2E);
        Ea[14] = ex2f_(a3.z * LOG2E); Ea[15] = ex2f_(a3.w * LOG2E);
    }

    auto step = [&](int t, int par, float (&Ecur)[16], float (&Enext)[16]) {
        // 1. ensure stage t+1 complete for this thread (<=2 groups pending)
        asm volatile("cp.async.wait_group 2;");

        // 2. poll V_t slot (one volatile LDS.64/thread), build exp2 entry
        float r;
        if (t == 0) {
            if (tid < NS) sEV[0][tid] = 1.f;
        } else {
            if (tid < NS) {
                unsigned a = vbase + (unsigned)((par * NS + tid) * 8);
                unsigned long long v;
                do { v = ld_vol64(a); } while ((unsigned)(v >> 32) != (unsigned)t);
                sEV[par][tid] = ex2f_(__uint_as_float((unsigned)v));
            }
        }
        __syncthreads();       // publishes sEV AND all warps' stage-(t+1) copies
        r = (t > 0) ? __uint_as_float((unsigned)ld_vol64(
                          vbase + (unsigned)(par * NS * 8)))
                    : 0.f;
        off += r;

        // 3. dot product + 8-lane reduce
        const float4* evp = (const float4*)sEV[par];
        float4 e0 = evp[sl], e1 = evp[sl + 8], e2 = evp[sl + 16], e3 = evp[sl + 24];
        float s0 = Ecur[0] * e0.x;
        s0 = fmaf(Ecur[1],  e0.y, s0); s0 = fmaf(Ecur[2],  e0.z, s0); s0 = fmaf(Ecur[3],  e0.w, s0);
        float s1 = Ecur[4] * e1.x;
        s1 = fmaf(Ecur[5],  e1.y, s1); s1 = fmaf(Ecur[6],  e1.z, s1); s1 = fmaf(Ecur[7],  e1.w, s1);
        float s2 = Ecur[8] * e2.x;
        s2 = fmaf(Ecur[9],  e2.y, s2); s2 = fmaf(Ecur[10], e2.z, s2); s2 = fmaf(Ecur[11], e2.w, s2);
        float s3 = Ecur[12] * e3.x;
        s3 = fmaf(Ecur[13], e3.y, s3); s3 = fmaf(Ecur[14], e3.z, s3); s3 = fmaf(Ecur[15], e3.w, s3);
        float s = (s0 + s1) + (s2 + s3);
        s += __shfl_xor_sync(FULLM, s, 1);
        s += __shfl_xor_sync(FULLM, s, 2);
        s += __shfl_xor_sync(FULLM, s, 4);

        // 4. send V_{t+1} IMMEDIATELY (parallel 4-lane fan-out)
        float vst = lg2f_(s) - r;
        if (sl < SUBS) {
            unsigned long long pkt = ((unsigned long long)(unsigned)(t + 1) << 32)
                                   | (unsigned long long)__float_as_uint(vst);
            unsigned voff = (unsigned)((((t + 1) & 1) * NS + irow) * 8);
            st_dsmem64(rV[sl] + voff, pkt);
        }

        // 5. SHADOW WORK (overlaps the DSMEM transit of V_{t+1}):
        //    issue prefetch for t+DIST, then transform stage t+1 -> Enext
        if (t + DIST < NT) {
            const char* src = (const char*)(base + (size_t)(t + DIST) * tstride);
            unsigned dst = rbase + ((t + DIST) % PIPE) * TILE_BYTES;
#pragma unroll
            for (int k2 = 0; k2 < 4; ++k2) {
                int o = (tid + k2 * NTHR) << 4;
                cp16(dst + o, src + o);
            }
        }
        asm volatile("cp.async.commit_group;");

        if (t + 1 < NT) {
            const float4* tp = ring + ((t + 1) % PIPE) * (TILE_BYTES / 16)
                             + rowL * (NS / 4) + sl;
            float4 a0 = tp[0], a1 = tp[8], a2 = tp[16], a3 = tp[24];
            Enext[0]  = ex2f_(a0.x * LOG2E); Enext[1]  = ex2f_(a0.y * LOG2E);
            Enext[2]  = ex2f_(a0.z * LOG2E); Enext[3]  = ex2f_(a0.w * LOG2E);
            Enext[4]  = ex2f_(a1.x * LOG2E); Enext[5]  = ex2f_(a1.y * LOG2E);
            Enext[6]  = ex2f_(a1.z * LOG2E); Enext[7]  = ex2f_(a1.w * LOG2E);
            Enext[8]  = ex2f_(a2.x * LOG2E); Enext[9]  = ex2f_(a2.y * LOG2E);
            Enext[10] = ex2f_(a2.z * LOG2E); Enext[11] = ex2f_(a2.w * LOG2E);
            Enext[12] = ex2f_(a3.x * LOG2E); Enext[13] = ex2f_(a3.y * LOG2E);
            Enext[14] = ex2f_(a3.z * LOG2E); Enext[15] = ex2f_(a3.w * LOG2E);
        }
    };

    for (int t = 0; t < NT; t += 2) {
        step(t,     0, Ea, Eb);
        step(t + 1, 1, Eb, Ea);
    }

    // ---- epilogue: drain tag NT (parity 0), then rank 0 reduces ----
    if (tid < NS) {
        unsigned ad = vbase + (unsigned)(tid * 8);
        unsigned long long v;
        do { v = ld_vol64(ad); } while ((unsigned)(v >> 32) != (unsigned)NT);
    }
    __syncthreads();
    if (sub == 0 && warp == 0) {
        float x0 = __uint_as_float((unsigned)sV[0][lane]);
        float x1 = __uint_as_float((unsigned)sV[0][lane + 32]);
        float x2 = __uint_as_float((unsigned)sV[0][lane + 64]);
        float x3 = __uint_as_float((unsigned)sV[0][lane + 96]);
        float s = ex2f_(x0) + ex2f_(x1) + ex2f_(x2) + ex2f_(x3);
#pragma unroll
        for (int o = 16; o; o >>= 1) s += __shfl_xor_sync(FULLM, s, o);
        if (lane == 0)
            out[bb] = 0.6931471805599453f * (off + lg2f_(s));
    }
    asm volatile("barrier.cluster.arrive.aligned;" ::: "memory");
    asm volatile("barrier.cluster.wait.aligned;"   ::: "memory");
}

extern "C" void kernel_launch(void* const* d_in, const int* in_sizes, int n_in,
                              void* d_out, int out_size)
{
    (void)in_sizes; (void)n_in; (void)out_size;
    const float* theta = (const float*)d_in[0];
    float* out = (float*)d_out;

    cudaFuncSetAttribute(viterbi_fwd,
                         cudaFuncAttributeMaxDynamicSharedMemorySize,
                         PIPE * TILE_BYTES);
    viterbi_fwd<<<NB * SUBS, NTHR, PIPE * TILE_BYTES>>>(theta, out);
}